// round 11
// baseline (speedup 1.0000x reference)
#include <cuda_runtime.h>
#include <math.h>

#define Bn   16
#define Tn   750
#define Fd   4096
#define Cd   20
#define KS   93
#define NROW (Bn*Tn)          // 12000

// ---- output layout (float elements) ----
#define OFF_SACT 0
#define OFF_SBKG 320
#define OFF_FACT 640
#define OFF_FBKG 6095488
#define OFF_FEAT 12190336
#define OFF_CSM  61342336

// ---- device scratch ----
__device__ float g_cas[NROW*Cd];
__device__ float g_mag[NROW];
__device__ int   g_idx_act[Bn*KS];
__device__ int   g_idx_bkg[Bn*KS];
__device__ float g_sact[Bn*Cd];

// ---- packed f32x2 helpers ----
__device__ __forceinline__ void fma2(unsigned long long& d,
                                     unsigned long long a, unsigned long long b) {
    asm("fma.rn.f32x2 %0, %1, %2, %0;" : "+l"(d) : "l"(a), "l"(b));
}
__device__ __forceinline__ unsigned long long mul2(unsigned long long a,
                                                   unsigned long long b) {
    unsigned long long d;
    asm("mul.rn.f32x2 %0, %1, %2;" : "=l"(d) : "l"(a), "l"(b));
    return d;
}
__device__ __forceinline__ float hadd2(unsigned long long v) {
    return __uint_as_float((unsigned)v) + __uint_as_float((unsigned)(v >> 32));
}
__device__ __forceinline__ double hadd2d(unsigned long long v) {
    return (double)__uint_as_float((unsigned)v) +
           (double)__uint_as_float((unsigned)(v >> 32));
}

// ---- cp.async helpers ----
__device__ __forceinline__ unsigned smem_u32(const void* p) {
    return (unsigned)__cvta_generic_to_shared(p);
}
__device__ __forceinline__ void cp16(unsigned dst, const void* src) {
    asm volatile("cp.async.cg.shared.global [%0], [%1], 16;"
                 :: "r"(dst), "l"(src) : "memory");
}
#define CP_COMMIT() asm volatile("cp.async.commit_group;" ::: "memory")
#define CP_WAIT(n)  asm volatile("cp.async.wait_group %0;" :: "n"(n) : "memory")

// ============================================================================
// K1: fused per-row pass, warp-exclusive rows, direct-LDG x/mask.
// 500 blocks x 256 threads (8 warps), 24 rows/block, 2 blocks/SM.
// Each warp owns 3 rows x ALL 20 classes -> x/mask loaded straight to regs
// (no staging, no per-sub-chunk barriers). Only W lives in smem,
// double-buffered via cp.async: W[2][20][128] f4 = 80KB + cass 1.92KB.
// acc[20][3] packed f32x2 (60 regs). One CP_WAIT+sync per W chunk (4 subs).
// ============================================================================
#define SM_TOTAL (81920 + 1920)

__global__ __launch_bounds__(256, 2) void k1_main(
    const ulonglong2* __restrict__ xg, const float4* __restrict__ Wg,
    const ulonglong2* __restrict__ mg, ulonglong2* __restrict__ featg,
    float* __restrict__ cas_sm)
{
    extern __shared__ char sm[];
    // W double buffer: each buf = 20 rows x 128 float4 (as ulonglong2)
    const ulonglong2* wbuf0 = (const ulonglong2*)sm;
    const ulonglong2* wbuf1 = (const ulonglong2*)(sm + 40960);
    float* cass = (float*)(sm + 81920);          // [24][Cd]
    const unsigned wsm0 = smem_u32(sm);

    const int tid  = threadIdx.x;
    const int lane = tid & 31;
    const int wrp  = tid >> 5;                   // 0..7
    const int row  = blockIdx.x * 24 + wrp * 3;  // this warp's first row

    const ulonglong2* xr0 = xg + (size_t)row * 1024;
    const ulonglong2* xr1 = xr0 + 1024;
    const ulonglong2* xr2 = xr1 + 1024;
    const ulonglong2* mr0 = mg + (size_t)row * 1024;
    const ulonglong2* mr1 = mr0 + 1024;
    const ulonglong2* mr2 = mr1 + 1024;
    ulonglong2* fr0 = featg + (size_t)row * 1024;
    ulonglong2* fr1 = fr0 + 1024;
    ulonglong2* fr2 = fr1 + 1024;

    unsigned long long acc[Cd][3];
    #pragma unroll
    for (int c = 0; c < Cd; c++) {
        acc[c][0] = 0ull; acc[c][1] = 0ull; acc[c][2] = 0ull;
    }
    unsigned long long ssq[3] = {0ull, 0ull, 0ull};

    // ---- prologue: cp.async W chunk 0 -> buf 0 ----
    {
        const float4* Wsrc = Wg;   // chunk 0
        #pragma unroll
        for (int k = tid, it = 0; it < 10; it++, k += 256) {
            int c = k >> 7, p = k & 127;
            cp16(wsm0 + (unsigned)k * 16u, Wsrc + c * 1024 + p);
        }
        CP_COMMIT();
    }

    for (int ch = 0; ch < 8; ch++) {
        CP_WAIT(0);
        __syncthreads();
        if (ch < 7) {   // prefetch next W chunk into the other buffer
            const float4* Wsrc = Wg + (ch + 1) * 128;
            unsigned dst = wsm0 + (unsigned)(((ch + 1) & 1) ? 40960 : 0);
            #pragma unroll
            for (int k = tid, it = 0; it < 10; it++, k += 256) {
                int c = k >> 7, p = k & 127;
                cp16(dst + (unsigned)k * 16u, Wsrc + c * 1024 + p);
            }
            CP_COMMIT();
        }
        const ulonglong2* wb = (ch & 1) ? wbuf1 : wbuf0;

        #pragma unroll
        for (int it = 0; it < 4; it++) {
            const int fi = ch * 128 + it * 32 + lane;
            unsigned long long xlo[3], xhi[3];
            // rows 0,1 (paired for MLP without blowing registers)
            {
                ulonglong2 xv0 = __ldg(xr0 + fi);
                ulonglong2 mv0 = __ldcs(mr0 + fi);
                ulonglong2 xv1 = __ldg(xr1 + fi);
                ulonglong2 mv1 = __ldcs(mr1 + fi);
                __stcs(fr0 + fi, xv0);
                __stcs(fr1 + fi, xv1);
                fma2(ssq[0], xv0.x, xv0.x); fma2(ssq[0], xv0.y, xv0.y);
                fma2(ssq[1], xv1.x, xv1.x); fma2(ssq[1], xv1.y, xv1.y);
                xlo[0] = mul2(xv0.x, mv0.x); xhi[0] = mul2(xv0.y, mv0.y);
                xlo[1] = mul2(xv1.x, mv1.x); xhi[1] = mul2(xv1.y, mv1.y);
            }
            // row 2
            {
                ulonglong2 xv2 = __ldg(xr2 + fi);
                ulonglong2 mv2 = __ldcs(mr2 + fi);
                __stcs(fr2 + fi, xv2);
                fma2(ssq[2], xv2.x, xv2.x); fma2(ssq[2], xv2.y, xv2.y);
                xlo[2] = mul2(xv2.x, mv2.x); xhi[2] = mul2(xv2.y, mv2.y);
            }
            const int wbi = it * 32 + lane;
            #pragma unroll
            for (int c = 0; c < Cd; c++) {
                ulonglong2 wv = wb[c * 128 + wbi];
                fma2(acc[c][0], wv.x, xlo[0]); fma2(acc[c][0], wv.y, xhi[0]);
                fma2(acc[c][1], wv.x, xlo[1]); fma2(acc[c][1], wv.y, xhi[1]);
                fma2(acc[c][2], wv.x, xlo[2]); fma2(acc[c][2], wv.y, xhi[2]);
            }
        }
    }

    // ---- warp-local cas reduction (3 rows x 20 classes per warp) ----
    #pragma unroll
    for (int c = 0; c < Cd; c++) {
        #pragma unroll
        for (int r = 0; r < 3; r++) {
            float s2 = hadd2(acc[c][r]);
            s2 += __shfl_down_sync(0xffffffffu, s2, 16);
            s2 += __shfl_down_sync(0xffffffffu, s2, 8);
            s2 += __shfl_down_sync(0xffffffffu, s2, 4);
            s2 += __shfl_down_sync(0xffffffffu, s2, 2);
            s2 += __shfl_down_sync(0xffffffffu, s2, 1);
            if (lane == 0) {
                cass[(wrp * 3 + r) * Cd + c] = s2;
                g_cas[(row + r) * Cd + c]    = s2;
            }
        }
    }
    // ---- mag (fp64 cross-lane reduce) ----
    #pragma unroll
    for (int r = 0; r < 3; r++) {
        double d = hadd2d(ssq[r]);
        d += __shfl_down_sync(0xffffffffu, d, 16);
        d += __shfl_down_sync(0xffffffffu, d, 8);
        d += __shfl_down_sync(0xffffffffu, d, 4);
        d += __shfl_down_sync(0xffffffffu, d, 2);
        d += __shfl_down_sync(0xffffffffu, d, 1);
        if (lane == 0) g_mag[row + r] = (float)sqrt(d);
    }
    __syncthreads();

    // ---- cas softmax over classes, one thread per row ----
    if (tid < 24) {
        int grow = blockIdx.x * 24 + tid;
        float m = -1e30f;
        #pragma unroll
        for (int c = 0; c < Cd; c++) m = fmaxf(m, cass[tid * Cd + c]);
        float e[Cd]; float s = 0.f;
        #pragma unroll
        for (int c = 0; c < Cd; c++) { e[c] = expf(cass[tid * Cd + c] - m); s += e[c]; }
        float inv = 1.f / s;
        #pragma unroll
        for (int c = 0; c < Cd; c++) cas_sm[grow * Cd + c] = e[c] * inv;
    }
}

// ============================================================================
// K23: merged top-k kernels. grid 136 x 256 threads.
// ============================================================================
__global__ void k23(const float* __restrict__ sel)
{
    __shared__ float sh[12000];
    __shared__ float wmax[8];
    const int tid = threadIdx.x;

    if (blockIdx.x < 96) {
        const int b = blockIdx.x / 6, chunk = blockIdx.x % 6;
        float* md  = sh;
        float* mrd = sh + Tn;

        float lmax = -1e30f;
        for (int i = tid; i < Tn; i += 256) {
            float m = g_mag[b * Tn + i];
            float s = sel[b * Tn + i];
            md[i] = m; mrd[i] = s;
            lmax = fmaxf(lmax, m);
        }
        for (int o = 16; o > 0; o >>= 1)
            lmax = fmaxf(lmax, __shfl_down_sync(0xffffffffu, lmax, o));
        if ((tid & 31) == 0) wmax[tid >> 5] = lmax;
        __syncthreads();
        float maxm = wmax[0];
        #pragma unroll
        for (int w = 1; w < 8; w++) maxm = fmaxf(maxm, wmax[w]);
        for (int i = tid; i < Tn; i += 256) {
            float m = md[i], s = mrd[i];
            md[i]  = m * s;
            mrd[i] = (maxm - m) * s;
        }
        __syncthreads();

        const int i = chunk * 125 + tid;
        if (tid < 125) {
            float v1 = md[i], v2 = mrd[i];
            int r1 = 0, r2 = 0;
            #pragma unroll 5
            for (int j = 0; j < Tn; j++) {
                float u1 = md[j];
                r1 += (int)(u1 > v1) + (int)((u1 == v1) & (j < i));
                float u2 = mrd[j];
                r2 += (int)(u2 > v2) + (int)((u2 == v2) & (j < i));
            }
            if (r1 < KS) g_idx_act[b * KS + r1] = i;
            if (r2 < KS) g_idx_bkg[b * KS + r2] = i;
        }
    } else {
        const int w = tid >> 5, lane = tid & 31;
        const int pair = (blockIdx.x - 96) * 8 + w;   // 0..319
        const int b = pair / Cd, c = pair % Cd;
        unsigned* key = (unsigned*)(sh + w * 1500);
        float*    col = sh + w * 1500 + Tn;

        for (int i = lane; i < Tn; i += 32) {
            float v = g_cas[(b * Tn + i) * Cd + c];
            col[i] = v;
            unsigned u = __float_as_uint(v);
            key[i] = (u & 0x80000000u) ? ~u : (u | 0x80000000u);
        }
        __syncwarp();

        unsigned prefix = 0u;
        for (int bit = 31; bit >= 0; --bit) {
            unsigned cand = prefix | (1u << bit);
            int cnt = 0;
            for (int i = lane; i < Tn; i += 32) cnt += (int)(key[i] >= cand);
            cnt = (int)__reduce_add_sync(0xffffffffu, (unsigned)cnt);
            if (cnt >= KS) prefix = cand;
        }
        float thr;
        { unsigned u = prefix; u = (u & 0x80000000u) ? (u & 0x7fffffffu) : ~u;
          thr = __uint_as_float(u); }

        int cg = 0; float s = 0.f;
        for (int i = lane; i < Tn; i += 32)
            if (key[i] > prefix) { cg++; s += col[i]; }
        cg = (int)__reduce_add_sync(0xffffffffu, (unsigned)cg);
        for (int o = 16; o > 0; o >>= 1) s += __shfl_down_sync(0xffffffffu, s, o);
        if (lane == 0)
            g_sact[b * Cd + c] = (s + (float)(KS - cg) * thr) * (1.f / (float)KS);
    }
}

// ============================================================================
// K45: merged tail. grid 2992 x 256 threads.
// ============================================================================
__global__ void k45(const float4* __restrict__ x4, float* __restrict__ out)
{
    __shared__ float red[12 * Cd];
    __shared__ float sb[Cd], sa[Cd], eb[Cd], ea[Cd];
    const int tid = threadIdx.x;

    if (blockIdx.x < 2976) {
        int idx = blockIdx.x;
        int z = (idx >= 1488) ? 1 : 0;
        idx -= z * 1488;
        const int b = idx / KS, k = idx % KS;
        const int* I = z ? g_idx_bkg : g_idx_act;
        const int t = I[b * KS + k];
        const float4* s = x4 + (long)(b * Tn + t) * 1024;
        float4* d = (float4*)out + (z ? (OFF_FBKG / 4) : (OFF_FACT / 4))
                    + (long)(b * KS + k) * 1024;
        for (int i = tid; i < 1024; i += 256) d[i] = s[i];
    } else {
        const int b = blockIdx.x - 2976;
        float* score_act = out + OFF_SACT;
        float* score_bkg = out + OFF_SBKG;

        if (tid < 240) {
            int c = tid % Cd, p = tid / Cd;
            float s = 0.f;
            for (int k = p; k < KS; k += 12) {
                int t = g_idx_bkg[b * KS + k];
                s += g_cas[(b * Tn + t) * Cd + c];
            }
            red[p * Cd + c] = s;
        }
        __syncthreads();
        if (tid < Cd) {
            float s = 0.f;
            #pragma unroll
            for (int p = 0; p < 12; p++) s += red[p * Cd + tid];
            sb[tid] = s * (1.f / (float)KS);
            sa[tid] = g_sact[b * Cd + tid];
        }
        __syncthreads();
        if (tid < Cd) {
            float mb = -1e30f, ma = -1e30f;
            #pragma unroll
            for (int j = 0; j < Cd; j++) { mb = fmaxf(mb, sb[j]); ma = fmaxf(ma, sa[j]); }
            eb[tid] = expf(sb[tid] - mb);
            ea[tid] = expf(sa[tid] - ma);
        }
        __syncthreads();
        if (tid < Cd) {
            float Sb = 0.f, Sa = 0.f;
            #pragma unroll
            for (int j = 0; j < Cd; j++) { Sb += eb[j]; Sa += ea[j]; }
            score_bkg[b * Cd + tid] = eb[tid] / Sb;
            score_act[b * Cd + tid] = ea[tid] / Sa;
        }
    }
}

// ============================================================================
extern "C" void kernel_launch(void* const* d_in, const int* in_sizes, int n_in,
                              void* d_out, int out_size)
{
    const float* x    = (const float*)d_in[0];
    const float* W    = (const float*)d_in[1];
    const float* mask = (const float*)d_in[2];
    const float* sel  = (const float*)d_in[3];
    float* out = (float*)d_out;

    cudaFuncSetAttribute(k1_main, cudaFuncAttributeMaxDynamicSharedMemorySize, SM_TOTAL);

    k1_main<<<NROW / 24, 256, SM_TOTAL>>>(
        (const ulonglong2*)x, (const float4*)W, (const ulonglong2*)mask,
        (ulonglong2*)(out + OFF_FEAT), out + OFF_CSM);
    k23<<<136, 256>>>(sel);
    k45<<<2992, 256>>>((const float4*)x, out);
}

// round 12
// speedup vs baseline: 2.8355x; 2.8355x over previous
#include <cuda_runtime.h>
#include <math.h>

#define Bn   16
#define Tn   750
#define Fd   4096
#define Cd   20
#define KS   93
#define NROW (Bn*Tn)          // 12000

// ---- output layout (float elements) ----
#define OFF_SACT 0
#define OFF_SBKG 320
#define OFF_FACT 640
#define OFF_FBKG 6095488
#define OFF_FEAT 12190336
#define OFF_CSM  61342336

// ---- device scratch ----
__device__ float g_cas[NROW*Cd];
__device__ float g_mag[NROW];
__device__ int   g_idx_act[Bn*KS];
__device__ int   g_idx_bkg[Bn*KS];
__device__ float g_sact[Bn*Cd];

// ---- cp.async helpers ----
__device__ __forceinline__ unsigned smem_u32(const void* p) {
    return (unsigned)__cvta_generic_to_shared(p);
}
__device__ __forceinline__ void cp16(unsigned dst, const void* src) {
    asm volatile("cp.async.cg.shared.global [%0], [%1], 16;"
                 :: "r"(dst), "l"(src) : "memory");
}
#define CP_COMMIT() asm volatile("cp.async.commit_group;" ::: "memory")
#define CP_WAIT(n)  asm volatile("cp.async.wait_group %0;" :: "n"(n) : "memory")

// ============================================================================
// K1: fused per-row pass. 750 blocks x 256 threads, 16 rows/block, 2 blk/SM.
// 8 warps = 4 row-groups x 2 class-warps; per warp 4 rows x 10 classes,
// scalar fp32 acc (proven R9 core). x/m: 3-stage cp.async ring (48KB,
// prefetch dist 2). W: cp.async double-buffer, chunk=64 f4 (2 subs, 40KB),
// same group stream -> no blocking W reloads. feat/ssq handled by cw==0
// warps from already-loaded xv. smem total 91392B.
// ============================================================================
#define SM_OFF_XS   0
#define SM_OFF_MS   24576
#define SM_OFF_W    49152
#define SM_OFF_CASS 90112
#define SM_TOTAL    91392

__global__ __launch_bounds__(256, 2) void k1_main(
    const float4* __restrict__ xg, const float4* __restrict__ Wg,
    const float4* __restrict__ mg, float4* __restrict__ featg,
    float* __restrict__ cas_sm)
{
    extern __shared__ char sm[];
    float4* xs   = (float4*)(sm + SM_OFF_XS);    // [3][16][32]
    float4* msb  = (float4*)(sm + SM_OFF_MS);    // [3][16][32]
    float4* smw  = (float4*)(sm + SM_OFF_W);     // [2][20][64]
    float*  cass = (float*)(sm + SM_OFF_CASS);   // [16][Cd]

    const int tid  = threadIdx.x;
    const int lane = tid & 31;
    const int wrp  = tid >> 5;           // 0..7
    const int rg   = wrp >> 1;           // row-group 0..3 -> rows rg*4..rg*4+3
    const int cw   = wrp & 1;            // class-warp -> classes cw*10..+9
    const int cbase = cw * 10;
    const int row0 = blockIdx.x * 16;

    // producer mapping: thread stages rows (wrp) and (wrp+8) at f4 pos lane
    const float4* xsrcA = xg + (size_t)(row0 + wrp)     * 1024 + lane;
    const float4* xsrcB = xg + (size_t)(row0 + wrp + 8) * 1024 + lane;
    const float4* msrcA = mg + (size_t)(row0 + wrp)     * 1024 + lane;
    const float4* msrcB = mg + (size_t)(row0 + wrp + 8) * 1024 + lane;
    const unsigned xsA = smem_u32(xs)  + (unsigned)(wrp * 32 + lane) * 16u;
    const unsigned xsB = xsA + 8u * 32u * 16u;
    const unsigned msA = smem_u32(msb) + (unsigned)(wrp * 32 + lane) * 16u;
    const unsigned msB = msA + 8u * 32u * 16u;
    const unsigned wsm = smem_u32(smw);

    float acc[10][4];
    #pragma unroll
    for (int c = 0; c < 10; c++)
        #pragma unroll
        for (int r = 0; r < 4; r++) acc[c][r] = 0.f;
    float ssq[4] = {0.f, 0.f, 0.f, 0.f};

    // ---- prologue ----
    // G0: xm stage for sub 0 + W chunk 0 -> buf 0
    cp16(xsA, xsrcA); cp16(xsB, xsrcB);
    cp16(msA, msrcA); cp16(msB, msrcB);
    #pragma unroll
    for (int i = 0; i < 5; i++) {
        int k = tid + i * 256;                    // 0..1279
        int c = k >> 6, p = k & 63;
        cp16(wsm + (unsigned)k * 16u, Wg + c * 1024 + p);
    }
    CP_COMMIT();
    // G1: xm stage for sub 1
    {
        unsigned so = 1u * 512u * 16u;
        cp16(xsA + so, xsrcA + 32); cp16(xsB + so, xsrcB + 32);
        cp16(msA + so, msrcA + 32); cp16(msB + so, msrcB + 32);
        CP_COMMIT();
    }

    #define COMPUTE_SUB(s)                                                      \
    {                                                                           \
        const int stg = (s) % 3;                                                \
        const int wbase = (((s) >> 1) & 1) * 1280 + ((s) & 1) * 32;             \
        float4 xm[4];                                                           \
        _Pragma("unroll")                                                       \
        for (int r = 0; r < 4; r++) {                                           \
            const int lrow = rg * 4 + r;                                        \
            float4 xv = xs[stg * 512 + lrow * 32 + lane];                       \
            float4 mv = msb[stg * 512 + lrow * 32 + lane];                      \
            if (cw == 0) {                                                      \
                featg[(size_t)(row0 + lrow) * 1024 + (s) * 32 + lane] = xv;     \
                ssq[r] += xv.x*xv.x + xv.y*xv.y + xv.z*xv.z + xv.w*xv.w;        \
            }                                                                   \
            xm[r].x = xv.x * mv.x; xm[r].y = xv.y * mv.y;                       \
            xm[r].z = xv.z * mv.z; xm[r].w = xv.w * mv.w;                       \
        }                                                                       \
        _Pragma("unroll")                                                       \
        for (int c = 0; c < 10; c++) {                                          \
            float4 wv = smw[wbase + (cbase + c) * 64 + lane];                   \
            _Pragma("unroll")                                                   \
            for (int r = 0; r < 4; r++) {                                       \
                float a = acc[c][r];                                            \
                a = fmaf(wv.x, xm[r].x, a);                                     \
                a = fmaf(wv.y, xm[r].y, a);                                     \
                a = fmaf(wv.z, xm[r].z, a);                                     \
                a = fmaf(wv.w, xm[r].w, a);                                     \
                acc[c][r] = a;                                                  \
            }                                                                   \
        }                                                                       \
    }

    // ---- main loop ----
    for (int s = 0; s < 31; s++) {
        CP_WAIT(1);
        __syncthreads();
        const int sp = s + 2;                     // prefetch target sub
        if (sp < 32) {
            unsigned so = (unsigned)(sp % 3) * 8192u;   // 512 f4 * 16B
            cp16(xsA + so, xsrcA + sp * 32);
            cp16(xsB + so, xsrcB + sp * 32);
            cp16(msA + so, msrcA + sp * 32);
            cp16(msB + so, msrcB + sp * 32);
            if ((sp & 1) == 0) {                  // W chunk sp/2 -> buf (sp/2)&1
                const int ch = sp >> 1;
                const float4* Wsrc = Wg + ch * 64;
                unsigned dst = wsm + (unsigned)((ch & 1) * 1280) * 16u;
                #pragma unroll
                for (int i = 0; i < 5; i++) {
                    int k = tid + i * 256;
                    int c = k >> 6, p = k & 63;
                    cp16(dst + (unsigned)k * 16u, Wsrc + c * 1024 + p);
                }
            }
            CP_COMMIT();
        }
        COMPUTE_SUB(s);
    }
    CP_WAIT(0);
    __syncthreads();
    COMPUTE_SUB(31);

    // ---- warp-local cas reduction (4 rows x 10 classes per warp) ----
    #pragma unroll
    for (int c = 0; c < 10; c++) {
        #pragma unroll
        for (int r = 0; r < 4; r++) {
            float s2 = acc[c][r];
            s2 += __shfl_down_sync(0xffffffffu, s2, 16);
            s2 += __shfl_down_sync(0xffffffffu, s2, 8);
            s2 += __shfl_down_sync(0xffffffffu, s2, 4);
            s2 += __shfl_down_sync(0xffffffffu, s2, 2);
            s2 += __shfl_down_sync(0xffffffffu, s2, 1);
            if (lane == 0) {
                int cc = cbase + c;
                int lrow = rg * 4 + r;
                cass[lrow * Cd + cc] = s2;
                g_cas[(row0 + lrow) * Cd + cc] = s2;
            }
        }
    }
    // ---- mag: cw==0 warp reduces its 4 rows (fp64 cross-lane) ----
    if (cw == 0) {
        #pragma unroll
        for (int r = 0; r < 4; r++) {
            double d = (double)ssq[r];
            d += __shfl_down_sync(0xffffffffu, d, 16);
            d += __shfl_down_sync(0xffffffffu, d, 8);
            d += __shfl_down_sync(0xffffffffu, d, 4);
            d += __shfl_down_sync(0xffffffffu, d, 2);
            d += __shfl_down_sync(0xffffffffu, d, 1);
            if (lane == 0) g_mag[row0 + rg * 4 + r] = (float)sqrt(d);
        }
    }
    __syncthreads();

    // ---- cas softmax over classes, one thread per row ----
    if (tid < 16) {
        int row = row0 + tid;
        float m = -1e30f;
        #pragma unroll
        for (int c = 0; c < Cd; c++) m = fmaxf(m, cass[tid * Cd + c]);
        float e[Cd]; float s = 0.f;
        #pragma unroll
        for (int c = 0; c < Cd; c++) { e[c] = expf(cass[tid * Cd + c] - m); s += e[c]; }
        float inv = 1.f / s;
        #pragma unroll
        for (int c = 0; c < Cd; c++) cas_sm[row * Cd + c] = e[c] * inv;
    }
}

// ============================================================================
// K23: merged top-k kernels. grid 136 x 256 threads.
// ============================================================================
__global__ void k23(const float* __restrict__ sel)
{
    __shared__ float sh[12000];
    __shared__ float wmax[8];
    const int tid = threadIdx.x;

    if (blockIdx.x < 96) {
        const int b = blockIdx.x / 6, chunk = blockIdx.x % 6;
        float* md  = sh;
        float* mrd = sh + Tn;

        float lmax = -1e30f;
        for (int i = tid; i < Tn; i += 256) {
            float m = g_mag[b * Tn + i];
            float s = sel[b * Tn + i];
            md[i] = m; mrd[i] = s;
            lmax = fmaxf(lmax, m);
        }
        for (int o = 16; o > 0; o >>= 1)
            lmax = fmaxf(lmax, __shfl_down_sync(0xffffffffu, lmax, o));
        if ((tid & 31) == 0) wmax[tid >> 5] = lmax;
        __syncthreads();
        float maxm = wmax[0];
        #pragma unroll
        for (int w = 1; w < 8; w++) maxm = fmaxf(maxm, wmax[w]);
        for (int i = tid; i < Tn; i += 256) {
            float m = md[i], s = mrd[i];
            md[i]  = m * s;
            mrd[i] = (maxm - m) * s;
        }
        __syncthreads();

        const int i = chunk * 125 + tid;
        if (tid < 125) {
            float v1 = md[i], v2 = mrd[i];
            int r1 = 0, r2 = 0;
            #pragma unroll 5
            for (int j = 0; j < Tn; j++) {
                float u1 = md[j];
                r1 += (int)(u1 > v1) + (int)((u1 == v1) & (j < i));
                float u2 = mrd[j];
                r2 += (int)(u2 > v2) + (int)((u2 == v2) & (j < i));
            }
            if (r1 < KS) g_idx_act[b * KS + r1] = i;
            if (r2 < KS) g_idx_bkg[b * KS + r2] = i;
        }
    } else {
        const int w = tid >> 5, lane = tid & 31;
        const int pair = (blockIdx.x - 96) * 8 + w;   // 0..319
        const int b = pair / Cd, c = pair % Cd;
        unsigned* key = (unsigned*)(sh + w * 1500);
        float*    col = sh + w * 1500 + Tn;

        for (int i = lane; i < Tn; i += 32) {
            float v = g_cas[(b * Tn + i) * Cd + c];
            col[i] = v;
            unsigned u = __float_as_uint(v);
            key[i] = (u & 0x80000000u) ? ~u : (u | 0x80000000u);
        }
        __syncwarp();

        unsigned prefix = 0u;
        for (int bit = 31; bit >= 0; --bit) {
            unsigned cand = prefix | (1u << bit);
            int cnt = 0;
            for (int i = lane; i < Tn; i += 32) cnt += (int)(key[i] >= cand);
            cnt = (int)__reduce_add_sync(0xffffffffu, (unsigned)cnt);
            if (cnt >= KS) prefix = cand;
        }
        float thr;
        { unsigned u = prefix; u = (u & 0x80000000u) ? (u & 0x7fffffffu) : ~u;
          thr = __uint_as_float(u); }

        int cg = 0; float s = 0.f;
        for (int i = lane; i < Tn; i += 32)
            if (key[i] > prefix) { cg++; s += col[i]; }
        cg = (int)__reduce_add_sync(0xffffffffu, (unsigned)cg);
        for (int o = 16; o > 0; o >>= 1) s += __shfl_down_sync(0xffffffffu, s, o);
        if (lane == 0)
            g_sact[b * Cd + c] = (s + (float)(KS - cg) * thr) * (1.f / (float)KS);
    }
}

// ============================================================================
// K45: merged tail. grid 2992 x 256 threads.
// ============================================================================
__global__ void k45(const float4* __restrict__ x4, float* __restrict__ out)
{
    __shared__ float red[12 * Cd];
    __shared__ float sb[Cd], sa[Cd], eb[Cd], ea[Cd];
    const int tid = threadIdx.x;

    if (blockIdx.x < 2976) {
        int idx = blockIdx.x;
        int z = (idx >= 1488) ? 1 : 0;
        idx -= z * 1488;
        const int b = idx / KS, k = idx % KS;
        const int* I = z ? g_idx_bkg : g_idx_act;
        const int t = I[b * KS + k];
        const float4* s = x4 + (long)(b * Tn + t) * 1024;
        float4* d = (float4*)out + (z ? (OFF_FBKG / 4) : (OFF_FACT / 4))
                    + (long)(b * KS + k) * 1024;
        for (int i = tid; i < 1024; i += 256) d[i] = s[i];
    } else {
        const int b = blockIdx.x - 2976;
        float* score_act = out + OFF_SACT;
        float* score_bkg = out + OFF_SBKG;

        if (tid < 240) {
            int c = tid % Cd, p = tid / Cd;
            float s = 0.f;
            for (int k = p; k < KS; k += 12) {
                int t = g_idx_bkg[b * KS + k];
                s += g_cas[(b * Tn + t) * Cd + c];
            }
            red[p * Cd + c] = s;
        }
        __syncthreads();
        if (tid < Cd) {
            float s = 0.f;
            #pragma unroll
            for (int p = 0; p < 12; p++) s += red[p * Cd + tid];
            sb[tid] = s * (1.f / (float)KS);
            sa[tid] = g_sact[b * Cd + tid];
        }
        __syncthreads();
        if (tid < Cd) {
            float mb = -1e30f, ma = -1e30f;
            #pragma unroll
            for (int j = 0; j < Cd; j++) { mb = fmaxf(mb, sb[j]); ma = fmaxf(ma, sa[j]); }
            eb[tid] = expf(sb[tid] - mb);
            ea[tid] = expf(sa[tid] - ma);
        }
        __syncthreads();
        if (tid < Cd) {
            float Sb = 0.f, Sa = 0.f;
            #pragma unroll
            for (int j = 0; j < Cd; j++) { Sb += eb[j]; Sa += ea[j]; }
            score_bkg[b * Cd + tid] = eb[tid] / Sb;
            score_act[b * Cd + tid] = ea[tid] / Sa;
        }
    }
}

// ============================================================================
extern "C" void kernel_launch(void* const* d_in, const int* in_sizes, int n_in,
                              void* d_out, int out_size)
{
    const float* x    = (const float*)d_in[0];
    const float* W    = (const float*)d_in[1];
    const float* mask = (const float*)d_in[2];
    const float* sel  = (const float*)d_in[3];
    float* out = (float*)d_out;

    cudaFuncSetAttribute(k1_main, cudaFuncAttributeMaxDynamicSharedMemorySize, SM_TOTAL);

    k1_main<<<NROW / 16, 256, SM_TOTAL>>>(
        (const float4*)x, (const float4*)W, (const float4*)mask,
        (float4*)(out + OFF_FEAT), out + OFF_CSM);
    k23<<<136, 256>>>(sel);
    k45<<<2992, 256>>>((const float4*)x, out);
}

// round 13
// speedup vs baseline: 3.1504x; 1.1111x over previous
#include <cuda_runtime.h>
#include <math.h>

#define Bn   16
#define Tn   750
#define Fd   4096
#define Cd   20
#define KS   93
#define NROW (Bn*Tn)          // 12000

// ---- output layout (float elements) ----
#define OFF_SACT 0
#define OFF_SBKG 320
#define OFF_FACT 640
#define OFF_FBKG 6095488
#define OFF_FEAT 12190336
#define OFF_CSM  61342336

// ---- device scratch ----
__device__ float g_cas[NROW*Cd];
__device__ float g_mag[NROW];
__device__ int   g_idx_act[Bn*KS];
__device__ int   g_idx_bkg[Bn*KS];
__device__ float g_sact[Bn*Cd];

// ---- cp.async helpers ----
__device__ __forceinline__ unsigned smem_u32(const void* p) {
    return (unsigned)__cvta_generic_to_shared(p);
}
__device__ __forceinline__ void cp16(unsigned dst, const void* src) {
    asm volatile("cp.async.cg.shared.global [%0], [%1], 16;"
                 :: "r"(dst), "l"(src) : "memory");
}
#define CP_COMMIT() asm volatile("cp.async.commit_group;" ::: "memory")
#define CP_WAIT(n)  asm volatile("cp.async.wait_group %0;" :: "n"(n) : "memory")

// ============================================================================
// K1: fused per-row pass. 600 blocks x 320 threads, 20 rows/block, 2 blk/SM
// -> grid = 2.03 waves over 296 slots (kills wave-quantization drain) and
// 20 warps/SM. 10 warps = 5 row-groups x 2 class-warps; per warp 4 rows x
// 10 classes, scalar fp32 acc (proven core). x/m: 3-stage cp.async ring
// (20 rows x 32 f4 per stage). W: cp.async double-buffer, chunk=64 f4
// (2 subs). feat via __stcs (don't evict W from L2).
// smem: xs 30720 + ms 30720 + W 40960 + cass 1600 = 104000B.
// ============================================================================
#define SM_OFF_XS   0
#define SM_OFF_MS   30720
#define SM_OFF_W    61440
#define SM_OFF_CASS 102400
#define SM_TOTAL    104000

__global__ __launch_bounds__(320, 2) void k1_main(
    const float4* __restrict__ xg, const float4* __restrict__ Wg,
    const float4* __restrict__ mg, float4* __restrict__ featg,
    float* __restrict__ cas_sm)
{
    extern __shared__ char sm[];
    float4* xs   = (float4*)(sm + SM_OFF_XS);    // [3][20][32]
    float4* msb  = (float4*)(sm + SM_OFF_MS);    // [3][20][32]
    float4* smw  = (float4*)(sm + SM_OFF_W);     // [2][20][64]
    float*  cass = (float*)(sm + SM_OFF_CASS);   // [20][Cd]

    const int tid  = threadIdx.x;
    const int lane = tid & 31;
    const int wrp  = tid >> 5;           // 0..9
    const int rg   = wrp >> 1;           // row-group 0..4 -> rows rg*4..rg*4+3
    const int cw   = wrp & 1;            // class-warp -> classes cw*10..+9
    const int cbase = cw * 10;
    const int row0 = blockIdx.x * 20;

    // producer mapping: thread stages rows (wrp) and (wrp+10) at f4 pos lane
    const float4* xsrcA = xg + (size_t)(row0 + wrp)      * 1024 + lane;
    const float4* xsrcB = xg + (size_t)(row0 + wrp + 10) * 1024 + lane;
    const float4* msrcA = mg + (size_t)(row0 + wrp)      * 1024 + lane;
    const float4* msrcB = mg + (size_t)(row0 + wrp + 10) * 1024 + lane;
    const unsigned xsA = smem_u32(xs)  + (unsigned)(wrp * 32 + lane) * 16u;
    const unsigned xsB = xsA + 10u * 32u * 16u;
    const unsigned msA = smem_u32(msb) + (unsigned)(wrp * 32 + lane) * 16u;
    const unsigned msB = msA + 10u * 32u * 16u;
    const unsigned wsm = smem_u32(smw);

    float acc[10][4];
    #pragma unroll
    for (int c = 0; c < 10; c++)
        #pragma unroll
        for (int r = 0; r < 4; r++) acc[c][r] = 0.f;
    float ssq[4] = {0.f, 0.f, 0.f, 0.f};

    // ---- prologue ----
    // G0: xm sub 0 + W chunk 0 -> buf 0
    cp16(xsA, xsrcA); cp16(xsB, xsrcB);
    cp16(msA, msrcA); cp16(msB, msrcB);
    #pragma unroll
    for (int i = 0; i < 4; i++) {
        int k = tid + i * 320;                    // 0..1279
        int c = k >> 6, p = k & 63;
        cp16(wsm + (unsigned)k * 16u, Wg + c * 1024 + p);
    }
    CP_COMMIT();
    // G1: xm sub 1
    {
        unsigned so = 1u * 640u * 16u;
        cp16(xsA + so, xsrcA + 32); cp16(xsB + so, xsrcB + 32);
        cp16(msA + so, msrcA + 32); cp16(msB + so, msrcB + 32);
        CP_COMMIT();
    }

    #define COMPUTE_SUB(s)                                                      \
    {                                                                           \
        const int stg = (s) % 3;                                                \
        const int wbase = (((s) >> 1) & 1) * 1280 + ((s) & 1) * 32;             \
        float4 xm[4];                                                           \
        _Pragma("unroll")                                                       \
        for (int r = 0; r < 4; r++) {                                           \
            const int lrow = rg * 4 + r;                                        \
            float4 xv = xs[stg * 640 + lrow * 32 + lane];                       \
            float4 mv = msb[stg * 640 + lrow * 32 + lane];                      \
            if (cw == 0) {                                                      \
                __stcs(&featg[(size_t)(row0 + lrow) * 1024 + (s) * 32 + lane],  \
                       xv);                                                     \
                ssq[r] += xv.x*xv.x + xv.y*xv.y + xv.z*xv.z + xv.w*xv.w;        \
            }                                                                   \
            xm[r].x = xv.x * mv.x; xm[r].y = xv.y * mv.y;                       \
            xm[r].z = xv.z * mv.z; xm[r].w = xv.w * mv.w;                       \
        }                                                                       \
        _Pragma("unroll")                                                       \
        for (int c = 0; c < 10; c++) {                                          \
            float4 wv = smw[wbase + (cbase + c) * 64 + lane];                   \
            _Pragma("unroll")                                                   \
            for (int r = 0; r < 4; r++) {                                       \
                float a = acc[c][r];                                            \
                a = fmaf(wv.x, xm[r].x, a);                                     \
                a = fmaf(wv.y, xm[r].y, a);                                     \
                a = fmaf(wv.z, xm[r].z, a);                                     \
                a = fmaf(wv.w, xm[r].w, a);                                     \
                acc[c][r] = a;                                                  \
            }                                                                   \
        }                                                                       \
    }

    // ---- main loop over 32 sub-chunks ----
    for (int s = 0; s < 31; s++) {
        CP_WAIT(1);
        __syncthreads();
        const int sp = s + 2;                     // prefetch target sub
        if (sp < 32) {
            unsigned so = (unsigned)(sp % 3) * 10240u;  // 640 f4 * 16B
            cp16(xsA + so, xsrcA + sp * 32);
            cp16(xsB + so, xsrcB + sp * 32);
            cp16(msA + so, msrcA + sp * 32);
            cp16(msB + so, msrcB + sp * 32);
            if ((sp & 1) == 0) {                  // W chunk sp/2 -> buf (sp/2)&1
                const int ch = sp >> 1;
                const float4* Wsrc = Wg + ch * 64;
                unsigned dst = wsm + (unsigned)((ch & 1) * 1280) * 16u;
                #pragma unroll
                for (int i = 0; i < 4; i++) {
                    int k = tid + i * 320;
                    int c = k >> 6, p = k & 63;
                    cp16(dst + (unsigned)k * 16u, Wsrc + c * 1024 + p);
                }
            }
            CP_COMMIT();
        }
        COMPUTE_SUB(s);
    }
    CP_WAIT(0);
    __syncthreads();
    COMPUTE_SUB(31);

    // ---- warp-local cas reduction (4 rows x 10 classes per warp) ----
    #pragma unroll
    for (int c = 0; c < 10; c++) {
        #pragma unroll
        for (int r = 0; r < 4; r++) {
            float s2 = acc[c][r];
            s2 += __shfl_down_sync(0xffffffffu, s2, 16);
            s2 += __shfl_down_sync(0xffffffffu, s2, 8);
            s2 += __shfl_down_sync(0xffffffffu, s2, 4);
            s2 += __shfl_down_sync(0xffffffffu, s2, 2);
            s2 += __shfl_down_sync(0xffffffffu, s2, 1);
            if (lane == 0) {
                int cc = cbase + c;
                int lrow = rg * 4 + r;
                cass[lrow * Cd + cc] = s2;
                g_cas[(row0 + lrow) * Cd + cc] = s2;
            }
        }
    }
    // ---- mag: cw==0 warps reduce their 4 rows (fp64 cross-lane) ----
    if (cw == 0) {
        #pragma unroll
        for (int r = 0; r < 4; r++) {
            double d = (double)ssq[r];
            d += __shfl_down_sync(0xffffffffu, d, 16);
            d += __shfl_down_sync(0xffffffffu, d, 8);
            d += __shfl_down_sync(0xffffffffu, d, 4);
            d += __shfl_down_sync(0xffffffffu, d, 2);
            d += __shfl_down_sync(0xffffffffu, d, 1);
            if (lane == 0) g_mag[row0 + rg * 4 + r] = (float)sqrt(d);
        }
    }
    __syncthreads();

    // ---- cas softmax over classes, one thread per row ----
    if (tid < 20) {
        int row = row0 + tid;
        float m = -1e30f;
        #pragma unroll
        for (int c = 0; c < Cd; c++) m = fmaxf(m, cass[tid * Cd + c]);
        float e[Cd]; float s = 0.f;
        #pragma unroll
        for (int c = 0; c < Cd; c++) { e[c] = expf(cass[tid * Cd + c] - m); s += e[c]; }
        float inv = 1.f / s;
        #pragma unroll
        for (int c = 0; c < Cd; c++) cas_sm[row * Cd + c] = e[c] * inv;
    }
}

// ============================================================================
// K23: merged top-k kernels. grid 88 x 256 threads.
//  blocks [0,48): K2 — per-batch ordered top-93 (rank counting, 250 cand/blk)
//  blocks [48,88): K3 — warp-per-(b,c) radix select for score_act sums
// ============================================================================
__global__ void k23(const float* __restrict__ sel)
{
    __shared__ float sh[12000];
    __shared__ float wmax[8];
    const int tid = threadIdx.x;

    if (blockIdx.x < 48) {
        const int b = blockIdx.x / 3, chunk = blockIdx.x % 3;
        float* md  = sh;
        float* mrd = sh + Tn;

        float lmax = -1e30f;
        for (int i = tid; i < Tn; i += 256) {
            float m = g_mag[b * Tn + i];
            float s = sel[b * Tn + i];
            md[i] = m; mrd[i] = s;
            lmax = fmaxf(lmax, m);
        }
        for (int o = 16; o > 0; o >>= 1)
            lmax = fmaxf(lmax, __shfl_down_sync(0xffffffffu, lmax, o));
        if ((tid & 31) == 0) wmax[tid >> 5] = lmax;
        __syncthreads();
        float maxm = wmax[0];
        #pragma unroll
        for (int w = 1; w < 8; w++) maxm = fmaxf(maxm, wmax[w]);
        for (int i = tid; i < Tn; i += 256) {
            float m = md[i], s = mrd[i];
            md[i]  = m * s;
            mrd[i] = (maxm - m) * s;
        }
        __syncthreads();

        const int i = chunk * 250 + tid;
        if (tid < 250) {
            float v1 = md[i], v2 = mrd[i];
            int r1 = 0, r2 = 0;
            #pragma unroll 5
            for (int j = 0; j < Tn; j++) {
                float u1 = md[j];
                r1 += (int)(u1 > v1) + (int)((u1 == v1) & (j < i));
                float u2 = mrd[j];
                r2 += (int)(u2 > v2) + (int)((u2 == v2) & (j < i));
            }
            if (r1 < KS) g_idx_act[b * KS + r1] = i;
            if (r2 < KS) g_idx_bkg[b * KS + r2] = i;
        }
    } else {
        const int w = tid >> 5, lane = tid & 31;
        const int pair = (blockIdx.x - 48) * 8 + w;   // 0..319
        const int b = pair / Cd, c = pair % Cd;
        unsigned* key = (unsigned*)(sh + w * 1500);
        float*    col = sh + w * 1500 + Tn;

        for (int i = lane; i < Tn; i += 32) {
            float v = g_cas[(b * Tn + i) * Cd + c];
            col[i] = v;
            unsigned u = __float_as_uint(v);
            key[i] = (u & 0x80000000u) ? ~u : (u | 0x80000000u);
        }
        __syncwarp();

        unsigned prefix = 0u;
        for (int bit = 31; bit >= 0; --bit) {
            unsigned cand = prefix | (1u << bit);
            int cnt = 0;
            for (int i = lane; i < Tn; i += 32) cnt += (int)(key[i] >= cand);
            cnt = (int)__reduce_add_sync(0xffffffffu, (unsigned)cnt);
            if (cnt >= KS) prefix = cand;
        }
        float thr;
        { unsigned u = prefix; u = (u & 0x80000000u) ? (u & 0x7fffffffu) : ~u;
          thr = __uint_as_float(u); }

        int cg = 0; float s = 0.f;
        for (int i = lane; i < Tn; i += 32)
            if (key[i] > prefix) { cg++; s += col[i]; }
        cg = (int)__reduce_add_sync(0xffffffffu, (unsigned)cg);
        for (int o = 16; o > 0; o >>= 1) s += __shfl_down_sync(0xffffffffu, s, o);
        if (lane == 0)
            g_sact[b * Cd + c] = (s + (float)(KS - cg) * thr) * (1.f / (float)KS);
    }
}

// ============================================================================
// K45: merged tail. grid 2992 x 256 threads.
// ============================================================================
__global__ void k45(const float4* __restrict__ x4, float* __restrict__ out)
{
    __shared__ float red[12 * Cd];
    __shared__ float sb[Cd], sa[Cd], eb[Cd], ea[Cd];
    const int tid = threadIdx.x;

    if (blockIdx.x < 2976) {
        int idx = blockIdx.x;
        int z = (idx >= 1488) ? 1 : 0;
        idx -= z * 1488;
        const int b = idx / KS, k = idx % KS;
        const int* I = z ? g_idx_bkg : g_idx_act;
        const int t = I[b * KS + k];
        const float4* s = x4 + (long)(b * Tn + t) * 1024;
        float4* d = (float4*)out + (z ? (OFF_FBKG / 4) : (OFF_FACT / 4))
                    + (long)(b * KS + k) * 1024;
        for (int i = tid; i < 1024; i += 256) d[i] = s[i];
    } else {
        const int b = blockIdx.x - 2976;
        float* score_act = out + OFF_SACT;
        float* score_bkg = out + OFF_SBKG;

        if (tid < 240) {
            int c = tid % Cd, p = tid / Cd;
            float s = 0.f;
            for (int k = p; k < KS; k += 12) {
                int t = g_idx_bkg[b * KS + k];
                s += g_cas[(b * Tn + t) * Cd + c];
            }
            red[p * Cd + c] = s;
        }
        __syncthreads();
        if (tid < Cd) {
            float s = 0.f;
            #pragma unroll
            for (int p = 0; p < 12; p++) s += red[p * Cd + tid];
            sb[tid] = s * (1.f / (float)KS);
            sa[tid] = g_sact[b * Cd + tid];
        }
        __syncthreads();
        if (tid < Cd) {
            float mb = -1e30f, ma = -1e30f;
            #pragma unroll
            for (int j = 0; j < Cd; j++) { mb = fmaxf(mb, sb[j]); ma = fmaxf(ma, sa[j]); }
            eb[tid] = expf(sb[tid] - mb);
            ea[tid] = expf(sa[tid] - ma);
        }
        __syncthreads();
        if (tid < Cd) {
            float Sb = 0.f, Sa = 0.f;
            #pragma unroll
            for (int j = 0; j < Cd; j++) { Sb += eb[j]; Sa += ea[j]; }
            score_bkg[b * Cd + tid] = eb[tid] / Sb;
            score_act[b * Cd + tid] = ea[tid] / Sa;
        }
    }
}

// ============================================================================
extern "C" void kernel_launch(void* const* d_in, const int* in_sizes, int n_in,
                              void* d_out, int out_size)
{
    const float* x    = (const float*)d_in[0];
    const float* W    = (const float*)d_in[1];
    const float* mask = (const float*)d_in[2];
    const float* sel  = (const float*)d_in[3];
    float* out = (float*)d_out;

    cudaFuncSetAttribute(k1_main, cudaFuncAttributeMaxDynamicSharedMemorySize, SM_TOTAL);

    k1_main<<<NROW / 20, 320, SM_TOTAL>>>(
        (const float4*)x, (const float4*)W, (const float4*)mask,
        (float4*)(out + OFF_FEAT), out + OFF_CSM);
    k23<<<88, 256>>>(sel);
    k45<<<2992, 256>>>((const float4*)x, out);
}